// round 8
// baseline (speedup 1.0000x reference)
#include <cuda_runtime.h>
#include <math.h>

#define NU 50000
#define NI 50000
#define NN 100000
#define NE 1600000
#define NP 200000
#define H  64
#define SCAN_NBLK ((NN + 1023) / 1024)   // 98

// ---------------- device scratch ----------------
__device__ int   g_ocnt[NN];
__device__ int   g_icnt[NN];
__device__ float g_onorm[NN];
__device__ float g_innorm[NN];
__device__ int   g_off[NN];
__device__ int   g_cur[NN];
__device__ int   g_bsum[SCAN_NBLK];
__device__ int   g_csrc[NE];
__device__ float g_e0[(size_t)NN * H];
__device__ float g_agg0[(size_t)NN * H];    // layer-1 "embeddings"
__device__ float g_agg0s[(size_t)NN * H];   // agg0 * out_norm (prescaled for layer 2)
__device__ float g_xu[(size_t)NU * H];
__device__ float g_xi[(size_t)NI * H];

// ---------------- lean GEMM body: 24.6KB smem, double-buffered A and W ----------------
__device__ __forceinline__ void gemm_body(
    int gb, char* sh,
    const float* __restrict__ A1, const float* __restrict__ W1, const float* __restrict__ b1,
    float* __restrict__ C1, int M1,
    const float* __restrict__ A2, const float* __restrict__ W2, const float* __restrict__ b2,
    float* __restrict__ C2, int M2,
    int K, int doRelu, int nb1)
{
    float (*Ws)[16][64]  = (float(*)[16][64])sh;
    float (*As)[16][128] = (float(*)[16][128])(sh + 8192);

    const float* A; const float* W; const float* bias; float* C; int M, bm0;
    if (gb < nb1) {
        A = A1; W = W1; bias = b1; C = C1; M = M1; bm0 = gb * 128;
    } else {
        A = A2; W = W2; bias = b2; C = C2; M = M2; bm0 = (gb - nb1) * 128;
    }

    int t = threadIdx.x;
    int wk = t >> 4;
    int wc = t & 15;
    int lrow = t >> 1;
    int lq = (t & 1) * 8;
    int row = bm0 + lrow;
    bool rv = row < M;
    const float* Ar = A + (size_t)row * K;

    float4 p0 = make_float4(0.f, 0.f, 0.f, 0.f), p1 = p0, wv = p0;

#define FETCHA(k0) do { \
    if (rv) { p0 = *(const float4*)(Ar + (k0) + lq); p1 = *(const float4*)(Ar + (k0) + lq + 4); } \
} while (0)
#define FETCHW(k0) do { wv = *(const float4*)(W + (size_t)((k0) + wk) * 64 + wc * 4); } while (0)
#define STAGEA(buf) do { \
    As[buf][lq + 0][lrow] = p0.x; As[buf][lq + 1][lrow] = p0.y; \
    As[buf][lq + 2][lrow] = p0.z; As[buf][lq + 3][lrow] = p0.w; \
    As[buf][lq + 4][lrow] = p1.x; As[buf][lq + 5][lrow] = p1.y; \
    As[buf][lq + 6][lrow] = p1.z; As[buf][lq + 7][lrow] = p1.w; \
} while (0)
#define STAGEW(buf) do { *(float4*)&Ws[buf][wk][wc * 4] = wv; } while (0)

    FETCHA(0); FETCHW(0);
    STAGEA(0); STAGEW(0);
    __syncthreads();

    float acc[8][4];
#pragma unroll
    for (int i = 0; i < 8; i++)
#pragma unroll
        for (int j = 0; j < 4; j++) acc[i][j] = 0.f;

    int tx = t & 15;
    int ty = t >> 4;
    int nt = K >> 4;

    for (int tile = 0; tile < nt; tile++) {
        int buf = tile & 1;
        if (tile + 1 < nt) { FETCHA((tile + 1) << 4); FETCHW((tile + 1) << 4); }

#pragma unroll
        for (int k = 0; k < 16; k++) {
            float4 b  = *(const float4*)&Ws[buf][k][tx * 4];
            float4 x0 = *(const float4*)&As[buf][k][ty * 8];
            float4 x1 = *(const float4*)&As[buf][k][ty * 8 + 4];
            acc[0][0] += x0.x * b.x; acc[0][1] += x0.x * b.y; acc[0][2] += x0.x * b.z; acc[0][3] += x0.x * b.w;
            acc[1][0] += x0.y * b.x; acc[1][1] += x0.y * b.y; acc[1][2] += x0.y * b.z; acc[1][3] += x0.y * b.w;
            acc[2][0] += x0.z * b.x; acc[2][1] += x0.z * b.y; acc[2][2] += x0.z * b.z; acc[2][3] += x0.z * b.w;
            acc[3][0] += x0.w * b.x; acc[3][1] += x0.w * b.y; acc[3][2] += x0.w * b.z; acc[3][3] += x0.w * b.w;
            acc[4][0] += x1.x * b.x; acc[4][1] += x1.x * b.y; acc[4][2] += x1.x * b.z; acc[4][3] += x1.x * b.w;
            acc[5][0] += x1.y * b.x; acc[5][1] += x1.y * b.y; acc[5][2] += x1.y * b.z; acc[5][3] += x1.y * b.w;
            acc[6][0] += x1.z * b.x; acc[6][1] += x1.z * b.y; acc[6][2] += x1.z * b.z; acc[6][3] += x1.z * b.w;
            acc[7][0] += x1.w * b.x; acc[7][1] += x1.w * b.y; acc[7][2] += x1.w * b.z; acc[7][3] += x1.w * b.w;
        }

        if (tile + 1 < nt) {
            __syncthreads();
            STAGEA((tile + 1) & 1);
            STAGEW((tile + 1) & 1);
            __syncthreads();
        }
    }

    float bvals[4] = {0.f, 0.f, 0.f, 0.f};
    if (bias) {
#pragma unroll
        for (int j = 0; j < 4; j++) bvals[j] = bias[tx * 4 + j];
    }

#pragma unroll
    for (int r = 0; r < 8; r++) {
        int orow = bm0 + ty * 8 + r;
        if (orow < M) {
            float4 v;
            v.x = acc[r][0] + bvals[0];
            v.y = acc[r][1] + bvals[1];
            v.z = acc[r][2] + bvals[2];
            v.w = acc[r][3] + bvals[3];
            if (doRelu) {
                v.x = fmaxf(v.x, 0.f); v.y = fmaxf(v.y, 0.f);
                v.z = fmaxf(v.z, 0.f); v.w = fmaxf(v.w, 0.f);
            }
            *(float4*)(C + (size_t)orow * 64 + tx * 4) = v;
        }
    }
#undef FETCHA
#undef FETCHW
#undef STAGEA
#undef STAGEW
}

// ---------------- fused edge-stage + GEMM-chunk co-kernel ----------------
__global__ void __launch_bounds__(256, 4) csr_gemm_kernel(
    int stage, int nGemm, int gemmStart,
    const int* __restrict__ esrc, const int* __restrict__ edst,
    const float* __restrict__ A1, const float* __restrict__ W1, const float* __restrict__ b1,
    float* __restrict__ C1, int M1,
    const float* __restrict__ A2, const float* __restrict__ W2, const float* __restrict__ b2,
    float* __restrict__ C2, int M2,
    int K, int doRelu, int nb1, int nbTot)
{
    __shared__ char sh[24576];
    int tid = threadIdx.x;

    if ((int)blockIdx.x < nGemm) {
        int gb = gemmStart + blockIdx.x;
        if (gb < nbTot)
            gemm_body(gb, sh, A1, W1, b1, C1, M1, A2, W2, b2, C2, M2, K, doRelu, nb1);
        return;
    }
    int cb = blockIdx.x - nGemm;
    int base = (cb * 256 + tid) * 4;
    if (base >= NE) return;

    int4 s4 = *(const int4*)(esrc + base);
    int4 d4 = *(const int4*)(edst + base);
    if (stage == 1) {
        atomicAdd(&g_ocnt[s4.x], 1); atomicAdd(&g_icnt[d4.x], 1);
        atomicAdd(&g_ocnt[s4.y], 1); atomicAdd(&g_icnt[d4.y], 1);
        atomicAdd(&g_ocnt[s4.z], 1); atomicAdd(&g_icnt[d4.z], 1);
        atomicAdd(&g_ocnt[s4.w], 1); atomicAdd(&g_icnt[d4.w], 1);
    } else {
        g_csrc[atomicAdd(&g_cur[d4.x], 1)] = s4.x;
        g_csrc[atomicAdd(&g_cur[d4.y], 1)] = s4.y;
        g_csrc[atomicAdd(&g_cur[d4.z], 1)] = s4.z;
        g_csrc[atomicAdd(&g_cur[d4.w], 1)] = s4.w;
    }
}

// ---------------- standalone small kernels ----------------
__global__ void clear_kernel() {
    int i = blockIdx.x * blockDim.x + threadIdx.x;
    if (i < NN) { g_ocnt[i] = 0; g_icnt[i] = 0; }
}

__global__ void scan1_kernel() {
    __shared__ int wsum[8];
    int tid = threadIdx.x;
    int base = blockIdx.x * 1024 + tid * 4;
    int v0 = (base + 0 < NN) ? g_icnt[base + 0] : 0;
    int v1 = (base + 1 < NN) ? g_icnt[base + 1] : 0;
    int v2 = (base + 2 < NN) ? g_icnt[base + 2] : 0;
    int v3 = (base + 3 < NN) ? g_icnt[base + 3] : 0;
    int s1 = v0, s2 = v0 + v1, s3 = v0 + v1 + v2, s = s3 + v3;
    int lane = tid & 31, wp = tid >> 5;
    int incl = s;
#pragma unroll
    for (int o = 1; o < 32; o <<= 1) {
        int n = __shfl_up_sync(0xffffffffu, incl, o);
        if (lane >= o) incl += n;
    }
    if (lane == 31) wsum[wp] = incl;
    __syncthreads();
    int wbase = 0;
    for (int k = 0; k < wp; k++) wbase += wsum[k];
    int et = wbase + incl - s;
    if (base + 0 < NN) g_off[base + 0] = et;
    if (base + 1 < NN) g_off[base + 1] = et + s1;
    if (base + 2 < NN) g_off[base + 2] = et + s2;
    if (base + 3 < NN) g_off[base + 3] = et + s3;
    if (tid == 255) g_bsum[blockIdx.x] = wbase + incl;
}

__global__ void scan3_kernel() {
    __shared__ int sboff[SCAN_NBLK];
    __shared__ int wsum[4];
    int tid = threadIdx.x;
    if (tid < 128) {
        int v = (tid < SCAN_NBLK) ? g_bsum[tid] : 0;
        int lane = tid & 31, wp = tid >> 5;
        int incl = v;
#pragma unroll
        for (int o = 1; o < 32; o <<= 1) {
            int n = __shfl_up_sync(0xffffffffu, incl, o);
            if (lane >= o) incl += n;
        }
        if (lane == 31) wsum[wp] = incl;
        __syncthreads();
        int wbase = 0;
        for (int k = 0; k < wp; k++) wbase += wsum[k];
        if (tid < SCAN_NBLK) sboff[tid] = wbase + incl - v;
    } else {
        __syncthreads();
    }
    __syncthreads();
    int i = blockIdx.x * blockDim.x + tid;
    if (i < NN) {
        int o = g_off[i] + sboff[i >> 10];
        g_off[i] = o;
        g_cur[i] = o;
        g_onorm[i]  = rsqrtf(fmaxf((float)g_ocnt[i], 1.0f));
        g_innorm[i] = rsqrtf(fmaxf((float)g_icnt[i], 1.0f));
    }
}

// ---------------- GCN layer 1: gather, 2 edges per warp (half-warp float4) ----------------
__global__ void gather1_kernel() {
    int gw = (blockIdx.x * blockDim.x + threadIdx.x) >> 5;
    int lane = threadIdx.x & 31;
    if (gw >= NN) return;
    int start = g_off[gw];
    int deg = g_icnt[gw];
    int half = lane & 16;
    int col = lane & 15;
    float4 acc = make_float4(0.f, 0.f, 0.f, 0.f);
    for (int j0 = 0; j0 < deg; j0 += 32) {
        int n = deg - j0; if (n > 32) n = 32;
        int idx = 0; float w = 0.f;
        if (lane < n) { idx = g_csrc[start + j0 + lane]; w = g_onorm[idx]; }
#pragma unroll
        for (int jj = 0; jj < 16; jj++) {
            int   s  = __shfl_sync(0xffffffffu, idx, jj | half);
            float wv = __shfl_sync(0xffffffffu, w,   jj | half);
            float4 r = ((const float4*)(g_e0 + (size_t)s * 64))[col];
            acc.x += wv * r.x; acc.y += wv * r.y;
            acc.z += wv * r.z; acc.w += wv * r.w;
        }
    }
    acc.x += __shfl_down_sync(0xffffffffu, acc.x, 16);
    acc.y += __shfl_down_sync(0xffffffffu, acc.y, 16);
    acc.z += __shfl_down_sync(0xffffffffu, acc.z, 16);
    acc.w += __shfl_down_sync(0xffffffffu, acc.w, 16);
    if (lane < 16) {
        float inn = g_innorm[gw];
        float onm = g_onorm[gw];
        float4 v  = make_float4(acc.x * inn, acc.y * inn, acc.z * inn, acc.w * inn);
        float4 vs = make_float4(v.x * onm, v.y * onm, v.z * onm, v.w * onm);
        ((float4*)(g_agg0  + (size_t)gw * 64))[lane] = v;
        ((float4*)(g_agg0s + (size_t)gw * 64))[lane] = vs;
    }
}

// ---------------- GCN layer 2 + final combine + xu/xi matvec, all fused ----------------
// Block: 256 threads (8 warps), 64 nodes (8 per warp). W1 both halves + b1 in smem.
__global__ void __launch_bounds__(256) gather2_fused_kernel(
    const float* __restrict__ side, const float* __restrict__ W1,
    const float* __restrict__ b1, float* __restrict__ out)
{
    __shared__ float Wus[64][64];   // W1[0:64][:]
    __shared__ float Wis[64][64];   // W1[64:128][:]
    __shared__ float b1s[64];

    int t = threadIdx.x;
    // stage weights: 8192 floats => 32 per thread (8 float4)
    for (int i = t; i < 64 * 16; i += 256) {
        int k = i >> 4, q = i & 15;
        *(float4*)&Wus[k][q * 4] = *(const float4*)(W1 + (size_t)k * 64 + q * 4);
        *(float4*)&Wis[k][q * 4] = *(const float4*)(W1 + (size_t)(k + 64) * 64 + q * 4);
    }
    if (t < 64) b1s[t] = b1[t];
    __syncthreads();

    int warp = t >> 5, lane = t & 31;
    int half = lane & 16;
    int col = lane & 15;
    int nodeBase = blockIdx.x * 64 + warp * 8;

    for (int g = 0; g < 8; g++) {
        int gw = nodeBase + g;
        if (gw >= NN) return;
        int start = g_off[gw];
        int deg = g_icnt[gw];
        float4 acc = make_float4(0.f, 0.f, 0.f, 0.f);
        for (int j0 = 0; j0 < deg; j0 += 32) {
            int n = deg - j0; if (n > 32) n = 32;
            int idx = 0; float w = 0.f;
            if (lane < n) { idx = g_csrc[start + j0 + lane]; w = 1.0f; }
#pragma unroll
            for (int jj = 0; jj < 16; jj++) {
                int   s  = __shfl_sync(0xffffffffu, idx, jj | half);
                float wv = __shfl_sync(0xffffffffu, w,   jj | half);
                float4 r = ((const float4*)(g_agg0s + (size_t)s * 64))[col];
                acc.x += wv * r.x; acc.y += wv * r.y;
                acc.z += wv * r.z; acc.w += wv * r.w;
            }
        }
        acc.x += __shfl_down_sync(0xffffffffu, acc.x, 16);
        acc.y += __shfl_down_sync(0xffffffffu, acc.y, 16);
        acc.z += __shfl_down_sync(0xffffffffu, acc.z, 16);
        acc.w += __shfl_down_sync(0xffffffffu, acc.w, 16);

        // final row (lanes 0-15 hold float4 cols 4l..4l+3)
        float4 row = make_float4(0.f, 0.f, 0.f, 0.f);
        bool isUser = gw < NU;
        if (lane < 16) {
            float inn3 = g_innorm[gw] * (1.0f / 3.0f);
            size_t base = (size_t)gw * 64;
            float4 e = ((const float4*)(g_e0 + base))[lane];
            float4 m = ((const float4*)(g_agg0 + base))[lane];
            row.x = e.x + 0.5f * m.x + inn3 * acc.x;
            row.y = e.y + 0.5f * m.y + inn3 * acc.y;
            row.z = e.z + 0.5f * m.z + inn3 * acc.z;
            row.w = e.w + 0.5f * m.w + inn3 * acc.w;
            if (!isUser) {
                float4 sd = ((const float4*)(side + (size_t)(gw - NU) * 64))[lane];
                row.x += sd.x; row.y += sd.y; row.z += sd.z; row.w += sd.w;
            }
            ((float4*)(out + base))[lane] = row;
        }

        // matvec: x[2*lane], x[2*lane+1] = row @ Wp (+ b1 for users)
        float (*Wp)[64] = isUser ? Wus : Wis;
        float xA = 0.f, xB = 0.f;
#pragma unroll
        for (int q = 0; q < 16; q++) {
            float fx = __shfl_sync(0xffffffffu, row.x, q);
            float fy = __shfl_sync(0xffffffffu, row.y, q);
            float fz = __shfl_sync(0xffffffffu, row.z, q);
            float fw = __shfl_sync(0xffffffffu, row.w, q);
            float2 w0 = *(const float2*)&Wp[4 * q + 0][2 * lane];
            float2 w1 = *(const float2*)&Wp[4 * q + 1][2 * lane];
            float2 w2 = *(const float2*)&Wp[4 * q + 2][2 * lane];
            float2 w3 = *(const float2*)&Wp[4 * q + 3][2 * lane];
            xA += fx * w0.x + fy * w1.x + fz * w2.x + fw * w3.x;
            xB += fx * w0.y + fy * w1.y + fz * w2.y + fw * w3.y;
        }
        if (isUser) {
            xA += b1s[2 * lane];
            xB += b1s[2 * lane + 1];
            *(float2*)(g_xu + (size_t)gw * 64 + 2 * lane) = make_float2(xA, xB);
        } else {
            *(float2*)(g_xi + (size_t)(gw - NU) * 64 + 2 * lane) = make_float2(xA, xB);
        }
    }
}

// ---------------- decode epilogue (float2 gathers) ----------------
__global__ void decode_kernel(const float* __restrict__ Tf, const float* __restrict__ Tcf,
                              const float* __restrict__ W1, const float* __restrict__ W2,
                              const int* __restrict__ userId, const int* __restrict__ posId,
                              const int* __restrict__ negId,
                              float* __restrict__ of, float* __restrict__ ocf) {
    __shared__ float w2s[64];
    __shared__ float w1l[64];
    int t = threadIdx.x;
    if (t < 64) {
        w2s[t] = W2[t];
        w1l[t] = W1[128 * 64 + t];
    }
    __syncthreads();

    int warp = t >> 5, lane = t & 31;
    int pair = blockIdx.x * 8 + warp;
    if (pair >= NP) return;

    int u  = userId[pair];
    int p  = posId[pair];
    int ng = negId[pair];

    float2 uv = *(const float2*)(g_xu + (size_t)u * 64 + 2 * lane);
    float2 pv = *(const float2*)(g_xi + (size_t)p * 64 + 2 * lane);
    float2 nv = *(const float2*)(g_xi + (size_t)ng * 64 + 2 * lane);
    float2 wl = *(const float2*)(w1l + 2 * lane);
    float2 w2 = *(const float2*)(w2s + 2 * lane);

    float tfp = Tf[pair],  tfn = Tf[pair + NP];
    float tcp = Tcf[pair], tcn = Tcf[pair + NP];

    auto combo = [&](float j0, float j1, float T) -> float {
        float x0 = uv.x + j0 + T * wl.x;
        float x1 = uv.y + j1 + T * wl.y;
        float e0 = x0 > 0.f ? x0 : (expf(x0) - 1.0f);
        float e1 = x1 > 0.f ? x1 : (expf(x1) - 1.0f);
        float s = e0 * w2.x + e1 * w2.y;
        s += __shfl_down_sync(0xffffffffu, s, 16);
        s += __shfl_down_sync(0xffffffffu, s, 8);
        s += __shfl_down_sync(0xffffffffu, s, 4);
        s += __shfl_down_sync(0xffffffffu, s, 2);
        s += __shfl_down_sync(0xffffffffu, s, 1);
        return s;
    };

    float rf_p = combo(pv.x, pv.y, tfp);
    float rf_n = combo(nv.x, nv.y, tfn);
    float rc_p = combo(pv.x, pv.y, tcp);
    float rc_n = combo(nv.x, nv.y, tcn);

    if (lane == 0) {
        of[pair]       = rf_p;
        of[pair + NP]  = rf_n;
        ocf[pair]      = rc_p;
        ocf[pair + NP] = rc_n;
    }
}

// ---------------- launch ----------------
extern "C" void kernel_launch(void* const* d_in, const int* in_sizes, int n_in,
                              void* d_out, int out_size) {
    const float* userF = (const float*)d_in[0];
    const float* itemF = (const float*)d_in[1];
    const float* side  = (const float*)d_in[2];
    const float* Tf    = (const float*)d_in[3];
    const float* Tcf   = (const float*)d_in[4];
    const float* Wu    = (const float*)d_in[5];
    const float* bu    = (const float*)d_in[6];
    const float* Wi    = (const float*)d_in[7];
    const float* bi    = (const float*)d_in[8];
    const float* W1    = (const float*)d_in[9];
    const float* b1    = (const float*)d_in[10];
    const float* W2    = (const float*)d_in[11];
    const int* esrc    = (const int*)d_in[12];
    const int* edst    = (const int*)d_in[13];
    const int* userId  = (const int*)d_in[14];
    const int* posId   = (const int*)d_in[15];
    const int* negId   = (const int*)d_in[16];

    float* out   = (float*)d_out;
    float* outLF = out + (size_t)NN * H;
    float* outLC = outLF + 2 * NP;

    float *pe0;
    cudaGetSymbolAddress((void**)&pe0, g_e0);

    int nb1 = (NU + 127) / 128;            // 391
    int nb2 = (NI + 127) / 128;            // 391
    int nbTot = nb1 + nb2;                 // 782
    int edgeBlocks = (NE / 4 + 255) / 256; // 1563

    clear_kernel<<<(NN + 255) / 256, 256>>>();

    // degree stage fused with first 300 GEMM blocks
    csr_gemm_kernel<<<300 + edgeBlocks, 256>>>(
        1, 300, 0, esrc, edst,
        userF, Wu, bu, pe0, NU,
        itemF, Wi, bi, pe0 + (size_t)NU * H, NI,
        128, 1, nb1, nbTot);

    scan1_kernel<<<SCAN_NBLK, 256>>>();
    scan3_kernel<<<(NN + 255) / 256, 256>>>();

    // fill stage fused with remaining 482 GEMM blocks
    csr_gemm_kernel<<<482 + edgeBlocks, 256>>>(
        5, 482, 300, esrc, edst,
        userF, Wu, bu, pe0, NU,
        itemF, Wi, bi, pe0 + (size_t)NU * H, NI,
        128, 1, nb1, nbTot);

    // GCN layer 1
    gather1_kernel<<<(NN * 32 + 255) / 256, 256>>>();

    // GCN layer 2 + final combine + xu/xi matvec (fused)
    gather2_fused_kernel<<<(NN + 63) / 64, 256>>>(side, W1, b1, out);

    // decode epilogue
    decode_kernel<<<(NP + 7) / 8, 256>>>(Tf, Tcf, W1, W2, userId, posId, negId, outLF, outLC);
}

// round 9
// speedup vs baseline: 1.3942x; 1.3942x over previous
#include <cuda_runtime.h>
#include <math.h>

#define NU 50000
#define NI 50000
#define NN 100000
#define NE 1600000
#define NP 200000
#define H  64
#define SCAN_NBLK ((NN + 1023) / 1024)   // 98

// ---------------- device scratch ----------------
__device__ int   g_ocnt[NN];
__device__ int   g_icnt[NN];
__device__ float g_onorm[NN];
__device__ float g_innorm[NN];
__device__ float g_rodeg[NN];               // 1/onorm = sqrt(max(out_deg,1))
__device__ int   g_off[NN];
__device__ int   g_cur[NN];
__device__ int   g_bsum[SCAN_NBLK];
__device__ float2 g_cpair[NE];              // (src as int bits, onorm[src])
__device__ float g_e0[(size_t)NN * H];
__device__ float g_agg0s[(size_t)NN * H];   // layer-1 out, prescaled by onorm
__device__ float g_xu[(size_t)NU * H];
__device__ float g_xi[(size_t)NI * H];

// ---------------- lean GEMM body: 24.6KB smem, double-buffered A and W ----------------
__device__ __forceinline__ void gemm_body(
    int gb, char* sh,
    const float* __restrict__ A1, const float* __restrict__ W1, const float* __restrict__ b1,
    float* __restrict__ C1, int M1,
    const float* __restrict__ A2, const float* __restrict__ W2, const float* __restrict__ b2,
    float* __restrict__ C2, int M2,
    int K, int doRelu, int nb1)
{
    float (*Ws)[16][64]  = (float(*)[16][64])sh;
    float (*As)[16][128] = (float(*)[16][128])(sh + 8192);

    const float* A; const float* W; const float* bias; float* C; int M, bm0;
    if (gb < nb1) {
        A = A1; W = W1; bias = b1; C = C1; M = M1; bm0 = gb * 128;
    } else {
        A = A2; W = W2; bias = b2; C = C2; M = M2; bm0 = (gb - nb1) * 128;
    }

    int t = threadIdx.x;
    int wk = t >> 4;
    int wc = t & 15;
    int lrow = t >> 1;
    int lq = (t & 1) * 8;
    int row = bm0 + lrow;
    bool rv = row < M;
    const float* Ar = A + (size_t)row * K;

    float4 p0 = make_float4(0.f, 0.f, 0.f, 0.f), p1 = p0, wv = p0;

#define FETCHA(k0) do { \
    if (rv) { p0 = *(const float4*)(Ar + (k0) + lq); p1 = *(const float4*)(Ar + (k0) + lq + 4); } \
} while (0)
#define FETCHW(k0) do { wv = *(const float4*)(W + (size_t)((k0) + wk) * 64 + wc * 4); } while (0)
#define STAGEA(buf) do { \
    As[buf][lq + 0][lrow] = p0.x; As[buf][lq + 1][lrow] = p0.y; \
    As[buf][lq + 2][lrow] = p0.z; As[buf][lq + 3][lrow] = p0.w; \
    As[buf][lq + 4][lrow] = p1.x; As[buf][lq + 5][lrow] = p1.y; \
    As[buf][lq + 6][lrow] = p1.z; As[buf][lq + 7][lrow] = p1.w; \
} while (0)
#define STAGEW(buf) do { *(float4*)&Ws[buf][wk][wc * 4] = wv; } while (0)

    FETCHA(0); FETCHW(0);
    STAGEA(0); STAGEW(0);
    __syncthreads();

    float acc[8][4];
#pragma unroll
    for (int i = 0; i < 8; i++)
#pragma unroll
        for (int j = 0; j < 4; j++) acc[i][j] = 0.f;

    int tx = t & 15;
    int ty = t >> 4;
    int nt = K >> 4;

    for (int tile = 0; tile < nt; tile++) {
        int buf = tile & 1;
        if (tile + 1 < nt) { FETCHA((tile + 1) << 4); FETCHW((tile + 1) << 4); }

#pragma unroll
        for (int k = 0; k < 16; k++) {
            float4 b  = *(const float4*)&Ws[buf][k][tx * 4];
            float4 x0 = *(const float4*)&As[buf][k][ty * 8];
            float4 x1 = *(const float4*)&As[buf][k][ty * 8 + 4];
            acc[0][0] += x0.x * b.x; acc[0][1] += x0.x * b.y; acc[0][2] += x0.x * b.z; acc[0][3] += x0.x * b.w;
            acc[1][0] += x0.y * b.x; acc[1][1] += x0.y * b.y; acc[1][2] += x0.y * b.z; acc[1][3] += x0.y * b.w;
            acc[2][0] += x0.z * b.x; acc[2][1] += x0.z * b.y; acc[2][2] += x0.z * b.z; acc[2][3] += x0.z * b.w;
            acc[3][0] += x0.w * b.x; acc[3][1] += x0.w * b.y; acc[3][2] += x0.w * b.z; acc[3][3] += x0.w * b.w;
            acc[4][0] += x1.x * b.x; acc[4][1] += x1.x * b.y; acc[4][2] += x1.x * b.z; acc[4][3] += x1.x * b.w;
            acc[5][0] += x1.y * b.x; acc[5][1] += x1.y * b.y; acc[5][2] += x1.y * b.z; acc[5][3] += x1.y * b.w;
            acc[6][0] += x1.z * b.x; acc[6][1] += x1.z * b.y; acc[6][2] += x1.z * b.z; acc[6][3] += x1.z * b.w;
            acc[7][0] += x1.w * b.x; acc[7][1] += x1.w * b.y; acc[7][2] += x1.w * b.z; acc[7][3] += x1.w * b.w;
        }

        if (tile + 1 < nt) {
            __syncthreads();
            STAGEA((tile + 1) & 1);
            STAGEW((tile + 1) & 1);
            __syncthreads();
        }
    }

    float bvals[4] = {0.f, 0.f, 0.f, 0.f};
    if (bias) {
#pragma unroll
        for (int j = 0; j < 4; j++) bvals[j] = bias[tx * 4 + j];
    }

#pragma unroll
    for (int r = 0; r < 8; r++) {
        int orow = bm0 + ty * 8 + r;
        if (orow < M) {
            float4 v;
            v.x = acc[r][0] + bvals[0];
            v.y = acc[r][1] + bvals[1];
            v.z = acc[r][2] + bvals[2];
            v.w = acc[r][3] + bvals[3];
            if (doRelu) {
                v.x = fmaxf(v.x, 0.f); v.y = fmaxf(v.y, 0.f);
                v.z = fmaxf(v.z, 0.f); v.w = fmaxf(v.w, 0.f);
            }
            *(float4*)(C + (size_t)orow * 64 + tx * 4) = v;
        }
    }
#undef FETCHA
#undef FETCHW
#undef STAGEA
#undef STAGEW
}

// ---------------- fused edge-stage + GEMM-chunk co-kernel ----------------
// stage 1 = degree count; stage 5 = CSR fill writing (src, onorm[src]) pairs
__global__ void __launch_bounds__(256, 4) csr_gemm_kernel(
    int stage, int nGemm, int gemmStart,
    const int* __restrict__ esrc, const int* __restrict__ edst,
    const float* __restrict__ A1, const float* __restrict__ W1, const float* __restrict__ b1,
    float* __restrict__ C1, int M1,
    const float* __restrict__ A2, const float* __restrict__ W2, const float* __restrict__ b2,
    float* __restrict__ C2, int M2,
    int K, int doRelu, int nb1, int nbTot)
{
    __shared__ char sh[24576];
    int tid = threadIdx.x;

    if ((int)blockIdx.x < nGemm) {
        int gb = gemmStart + blockIdx.x;
        if (gb < nbTot)
            gemm_body(gb, sh, A1, W1, b1, C1, M1, A2, W2, b2, C2, M2, K, doRelu, nb1);
        return;
    }
    int cb = blockIdx.x - nGemm;
    int base = (cb * 256 + tid) * 4;
    if (base >= NE) return;

    int4 s4 = *(const int4*)(esrc + base);
    int4 d4 = *(const int4*)(edst + base);
    if (stage == 1) {
        atomicAdd(&g_ocnt[s4.x], 1); atomicAdd(&g_icnt[d4.x], 1);
        atomicAdd(&g_ocnt[s4.y], 1); atomicAdd(&g_icnt[d4.y], 1);
        atomicAdd(&g_ocnt[s4.z], 1); atomicAdd(&g_icnt[d4.z], 1);
        atomicAdd(&g_ocnt[s4.w], 1); atomicAdd(&g_icnt[d4.w], 1);
    } else {
        float wx = g_onorm[s4.x], wy = g_onorm[s4.y];
        float wz = g_onorm[s4.z], ww = g_onorm[s4.w];
        g_cpair[atomicAdd(&g_cur[d4.x], 1)] = make_float2(__int_as_float(s4.x), wx);
        g_cpair[atomicAdd(&g_cur[d4.y], 1)] = make_float2(__int_as_float(s4.y), wy);
        g_cpair[atomicAdd(&g_cur[d4.z], 1)] = make_float2(__int_as_float(s4.z), wz);
        g_cpair[atomicAdd(&g_cur[d4.w], 1)] = make_float2(__int_as_float(s4.w), ww);
    }
}

// ---------------- standalone small kernels ----------------
__global__ void clear_kernel() {
    int i = blockIdx.x * blockDim.x + threadIdx.x;
    if (i < NN) { g_ocnt[i] = 0; g_icnt[i] = 0; }
}

__global__ void scan1_kernel() {
    __shared__ int wsum[8];
    int tid = threadIdx.x;
    int base = blockIdx.x * 1024 + tid * 4;
    int v0 = (base + 0 < NN) ? g_icnt[base + 0] : 0;
    int v1 = (base + 1 < NN) ? g_icnt[base + 1] : 0;
    int v2 = (base + 2 < NN) ? g_icnt[base + 2] : 0;
    int v3 = (base + 3 < NN) ? g_icnt[base + 3] : 0;
    int s1 = v0, s2 = v0 + v1, s3 = v0 + v1 + v2, s = s3 + v3;
    int lane = tid & 31, wp = tid >> 5;
    int incl = s;
#pragma unroll
    for (int o = 1; o < 32; o <<= 1) {
        int n = __shfl_up_sync(0xffffffffu, incl, o);
        if (lane >= o) incl += n;
    }
    if (lane == 31) wsum[wp] = incl;
    __syncthreads();
    int wbase = 0;
    for (int k = 0; k < wp; k++) wbase += wsum[k];
    int et = wbase + incl - s;
    if (base + 0 < NN) g_off[base + 0] = et;
    if (base + 1 < NN) g_off[base + 1] = et + s1;
    if (base + 2 < NN) g_off[base + 2] = et + s2;
    if (base + 3 < NN) g_off[base + 3] = et + s3;
    if (tid == 255) g_bsum[blockIdx.x] = wbase + incl;
}

// scan3: finalize offsets + norms (+rodeg). Each block re-derives block prefix.
__global__ void scan3_kernel() {
    __shared__ int sboff[SCAN_NBLK];
    __shared__ int wsum[4];
    int tid = threadIdx.x;
    if (tid < 128) {
        int v = (tid < SCAN_NBLK) ? g_bsum[tid] : 0;
        int lane = tid & 31, wp = tid >> 5;
        int incl = v;
#pragma unroll
        for (int o = 1; o < 32; o <<= 1) {
            int n = __shfl_up_sync(0xffffffffu, incl, o);
            if (lane >= o) incl += n;
        }
        if (lane == 31) wsum[wp] = incl;
        __syncthreads();
        int wbase = 0;
        for (int k = 0; k < wp; k++) wbase += wsum[k];
        if (tid < SCAN_NBLK) sboff[tid] = wbase + incl - v;
    } else {
        __syncthreads();
    }
    __syncthreads();
    int i = blockIdx.x * blockDim.x + tid;
    if (i < NN) {
        int o = g_off[i] + sboff[i >> 10];
        g_off[i] = o;
        g_cur[i] = o;
        float od = fmaxf((float)g_ocnt[i], 1.0f);
        g_onorm[i]  = rsqrtf(od);
        g_rodeg[i]  = sqrtf(od);
        g_innorm[i] = rsqrtf(fmaxf((float)g_icnt[i], 1.0f));
    }
}

// ---------------- plain dual GEMM ----------------
__global__ void __launch_bounds__(256, 4) gemm_dual(
    const float* __restrict__ A1, const float* __restrict__ W1, const float* __restrict__ b1,
    float* __restrict__ C1, int M1,
    const float* __restrict__ A2, const float* __restrict__ W2, const float* __restrict__ b2,
    float* __restrict__ C2, int M2,
    int K, int doRelu, int nb1)
{
    __shared__ char sh[24576];
    gemm_body(blockIdx.x, sh, A1, W1, b1, C1, M1, A2, W2, b2, C2, M2, K, doRelu, nb1);
}

// ---------------- GCN layer 1: warp/node, float2 rows, paired CSR ----------------
// agg0s = onorm * inn * sum(e0[src]*onorm[src])  (prescaled for layer 2)
__global__ void gather1_kernel() {
    int gw = (blockIdx.x * blockDim.x + threadIdx.x) >> 5;
    int lane = threadIdx.x & 31;
    if (gw >= NN) return;
    int start = g_off[gw];
    int deg = g_icnt[gw];
    float a0 = 0.f, a1 = 0.f;
    int nfull = deg & ~31;
    for (int j0 = 0; j0 < nfull; j0 += 32) {
        float2 pr = g_cpair[start + j0 + lane];
        int idx = __float_as_int(pr.x);
        float w = pr.y;
#pragma unroll
        for (int jj = 0; jj < 32; jj++) {
            int   s  = __shfl_sync(0xffffffffu, idx, jj);
            float wv = __shfl_sync(0xffffffffu, w, jj);
            float2 r = *(const float2*)(g_e0 + (size_t)s * 64 + 2 * lane);
            a0 += wv * r.x;
            a1 += wv * r.y;
        }
    }
    int rem = deg - nfull;
    if (rem) {
        int idx = 0; float w = 0.f;
        if (lane < rem) {
            float2 pr = g_cpair[start + nfull + lane];
            idx = __float_as_int(pr.x);
            w = pr.y;
        }
        for (int jj = 0; jj < rem; jj++) {
            int   s  = __shfl_sync(0xffffffffu, idx, jj);
            float wv = __shfl_sync(0xffffffffu, w, jj);
            float2 r = *(const float2*)(g_e0 + (size_t)s * 64 + 2 * lane);
            a0 += wv * r.x;
            a1 += wv * r.y;
        }
    }
    float sc = g_innorm[gw] * g_onorm[gw];
    *(float2*)(g_agg0s + (size_t)gw * 64 + 2 * lane) = make_float2(a0 * sc, a1 * sc);
}

// ---------------- GCN layer 2 + final combine (prescaled input) ----------------
// out[n] = e0 + 0.5*(agg0s*rodeg) + (1/3)*inn*sum(agg0s[src]) (+side for items)
__global__ void gather2_final_kernel(const float* __restrict__ side, float* __restrict__ out) {
    int gw = (blockIdx.x * blockDim.x + threadIdx.x) >> 5;
    int lane = threadIdx.x & 31;
    if (gw >= NN) return;
    int start = g_off[gw];
    int deg = g_icnt[gw];
    float a0 = 0.f, a1 = 0.f;
    int nfull = deg & ~31;
    for (int j0 = 0; j0 < nfull; j0 += 32) {
        int idx = __float_as_int(g_cpair[start + j0 + lane].x);
#pragma unroll
        for (int jj = 0; jj < 32; jj++) {
            int s = __shfl_sync(0xffffffffu, idx, jj);
            float2 r = *(const float2*)(g_agg0s + (size_t)s * 64 + 2 * lane);
            a0 += r.x;
            a1 += r.y;
        }
    }
    int rem = deg - nfull;
    if (rem) {
        int idx = 0;
        if (lane < rem) idx = __float_as_int(g_cpair[start + nfull + lane].x);
        for (int jj = 0; jj < rem; jj++) {
            int s = __shfl_sync(0xffffffffu, idx, jj);
            float2 r = *(const float2*)(g_agg0s + (size_t)s * 64 + 2 * lane);
            a0 += r.x;
            a1 += r.y;
        }
    }
    float inn3 = g_innorm[gw] * (1.0f / 3.0f);
    float half_rodeg = 0.5f * g_rodeg[gw];
    size_t base = (size_t)gw * 64 + 2 * lane;
    float2 e = *(const float2*)(g_e0 + base);
    float2 m = *(const float2*)(g_agg0s + base);
    float r0v = e.x + half_rodeg * m.x + inn3 * a0;
    float r1v = e.y + half_rodeg * m.y + inn3 * a1;
    if (gw >= NU) {
        float2 sd = *(const float2*)(side + (size_t)(gw - NU) * 64 + 2 * lane);
        r0v += sd.x;
        r1v += sd.y;
    }
    *(float2*)(out + base) = make_float2(r0v, r1v);
}

// ---------------- decode epilogue (float2 gathers) ----------------
__global__ void decode_kernel(const float* __restrict__ Tf, const float* __restrict__ Tcf,
                              const float* __restrict__ W1, const float* __restrict__ W2,
                              const int* __restrict__ userId, const int* __restrict__ posId,
                              const int* __restrict__ negId,
                              float* __restrict__ of, float* __restrict__ ocf) {
    __shared__ float w2s[64];
    __shared__ float w1l[64];
    int t = threadIdx.x;
    if (t < 64) {
        w2s[t] = W2[t];
        w1l[t] = W1[128 * 64 + t];
    }
    __syncthreads();

    int warp = t >> 5, lane = t & 31;
    int pair = blockIdx.x * 8 + warp;
    if (pair >= NP) return;

    int u  = userId[pair];
    int p  = posId[pair];
    int ng = negId[pair];

    float2 uv = *(const float2*)(g_xu + (size_t)u * 64 + 2 * lane);
    float2 pv = *(const float2*)(g_xi + (size_t)p * 64 + 2 * lane);
    float2 nv = *(const float2*)(g_xi + (size_t)ng * 64 + 2 * lane);
    float2 wl = *(const float2*)(w1l + 2 * lane);
    float2 w2 = *(const float2*)(w2s + 2 * lane);

    float tfp = Tf[pair],  tfn = Tf[pair + NP];
    float tcp = Tcf[pair], tcn = Tcf[pair + NP];

    auto combo = [&](float j0, float j1, float T) -> float {
        float x0 = uv.x + j0 + T * wl.x;
        float x1 = uv.y + j1 + T * wl.y;
        float e0 = x0 > 0.f ? x0 : (expf(x0) - 1.0f);
        float e1 = x1 > 0.f ? x1 : (expf(x1) - 1.0f);
        float s = e0 * w2.x + e1 * w2.y;
        s += __shfl_down_sync(0xffffffffu, s, 16);
        s += __shfl_down_sync(0xffffffffu, s, 8);
        s += __shfl_down_sync(0xffffffffu, s, 4);
        s += __shfl_down_sync(0xffffffffu, s, 2);
        s += __shfl_down_sync(0xffffffffu, s, 1);
        return s;
    };

    float rf_p = combo(pv.x, pv.y, tfp);
    float rf_n = combo(nv.x, nv.y, tfn);
    float rc_p = combo(pv.x, pv.y, tcp);
    float rc_n = combo(nv.x, nv.y, tcn);

    if (lane == 0) {
        of[pair]       = rf_p;
        of[pair + NP]  = rf_n;
        ocf[pair]      = rc_p;
        ocf[pair + NP] = rc_n;
    }
}

// ---------------- launch ----------------
extern "C" void kernel_launch(void* const* d_in, const int* in_sizes, int n_in,
                              void* d_out, int out_size) {
    const float* userF = (const float*)d_in[0];
    const float* itemF = (const float*)d_in[1];
    const float* side  = (const float*)d_in[2];
    const float* Tf    = (const float*)d_in[3];
    const float* Tcf   = (const float*)d_in[4];
    const float* Wu    = (const float*)d_in[5];
    const float* bu    = (const float*)d_in[6];
    const float* Wi    = (const float*)d_in[7];
    const float* bi    = (const float*)d_in[8];
    const float* W1    = (const float*)d_in[9];
    const float* b1    = (const float*)d_in[10];
    const float* W2    = (const float*)d_in[11];
    const int* esrc    = (const int*)d_in[12];
    const int* edst    = (const int*)d_in[13];
    const int* userId  = (const int*)d_in[14];
    const int* posId   = (const int*)d_in[15];
    const int* negId   = (const int*)d_in[16];

    float* out   = (float*)d_out;
    float* outI  = out + (size_t)NU * H;
    float* outLF = out + (size_t)NN * H;
    float* outLC = outLF + 2 * NP;

    float *pe0, *pxu, *pxi;
    cudaGetSymbolAddress((void**)&pe0, g_e0);
    cudaGetSymbolAddress((void**)&pxu, g_xu);
    cudaGetSymbolAddress((void**)&pxi, g_xi);

    int nb1 = (NU + 127) / 128;            // 391
    int nb2 = (NI + 127) / 128;            // 391
    int nbTot = nb1 + nb2;                 // 782
    int edgeBlocks = (NE / 4 + 255) / 256; // 1563

    clear_kernel<<<(NN + 255) / 256, 256>>>();

    // degree stage fused with first 300 GEMM blocks
    csr_gemm_kernel<<<300 + edgeBlocks, 256>>>(
        1, 300, 0, esrc, edst,
        userF, Wu, bu, pe0, NU,
        itemF, Wi, bi, pe0 + (size_t)NU * H, NI,
        128, 1, nb1, nbTot);

    scan1_kernel<<<SCAN_NBLK, 256>>>();
    scan3_kernel<<<(NN + 255) / 256, 256>>>();

    // fill stage (writes (src, w) pairs) fused with remaining 482 GEMM blocks
    csr_gemm_kernel<<<482 + edgeBlocks, 256>>>(
        5, 482, 300, esrc, edst,
        userF, Wu, bu, pe0, NU,
        itemF, Wi, bi, pe0 + (size_t)NU * H, NI,
        128, 1, nb1, nbTot);

    // GCN layers
    gather1_kernel<<<(NN * 32 + 255) / 256, 256>>>();
    gather2_final_kernel<<<(NN * 32 + 255) / 256, 256>>>(side, out);

    // per-node decode transforms
    gemm_dual<<<nbTot, 256>>>(out,  W1,           b1,      pxu, NU,
                              outI, W1 + 64 * 64, nullptr, pxi, NI,
                              64, 0, nb1);

    // decode epilogue
    decode_kernel<<<(NP + 7) / 8, 256>>>(Tf, Tcf, W1, W2, userId, posId, negId, outLF, outLC);
}

// round 10
// speedup vs baseline: 1.4052x; 1.0079x over previous
#include <cuda_runtime.h>
#include <cuda_fp16.h>
#include <math.h>

#define NU 50000
#define NI 50000
#define NN 100000
#define NE 1600000
#define NP 200000
#define H  64
#define SCAN_NBLK ((NN + 1023) / 1024)   // 98

// ---------------- device scratch ----------------
__device__ int   g_ocnt[NN];
__device__ int   g_icnt[NN];
__device__ float g_onorm[NN];
__device__ float g_innorm[NN];
__device__ float g_rodeg[NN];               // sqrt(max(out_deg,1))
__device__ int   g_off[NN];
__device__ int   g_cur[NN];
__device__ int   g_bsum[SCAN_NBLK];
__device__ float2 g_cpair[NE];              // (src as int bits, onorm[src])
__device__ float g_e0[(size_t)NN * H];
__device__ __half2 g_e0h[(size_t)NN * 32];      // fp16 mirror of e0 (gather reads)
__device__ float g_agg0s[(size_t)NN * H];   // layer-1 out, prescaled by onorm (fp32)
__device__ __half2 g_agg0sh[(size_t)NN * 32];   // fp16 mirror (gather reads)
__device__ float g_xu[(size_t)NU * H];
__device__ float g_xi[(size_t)NI * H];

// ---------------- lean GEMM body: 24.6KB smem, double-buffered A and W ----------------
// Optionally writes an fp16x2 mirror of C (halfC != nullptr).
__device__ __forceinline__ void gemm_body(
    int gb, char* sh,
    const float* __restrict__ A1, const float* __restrict__ W1, const float* __restrict__ b1,
    float* __restrict__ C1, __half2* __restrict__ H1, int M1,
    const float* __restrict__ A2, const float* __restrict__ W2, const float* __restrict__ b2,
    float* __restrict__ C2, __half2* __restrict__ H2, int M2,
    int K, int doRelu, int nb1)
{
    float (*Ws)[16][64]  = (float(*)[16][64])sh;
    float (*As)[16][128] = (float(*)[16][128])(sh + 8192);

    const float* A; const float* W; const float* bias; float* C; __half2* halfC; int M, bm0;
    if (gb < nb1) {
        A = A1; W = W1; bias = b1; C = C1; halfC = H1; M = M1; bm0 = gb * 128;
    } else {
        A = A2; W = W2; bias = b2; C = C2; halfC = H2; M = M2; bm0 = (gb - nb1) * 128;
    }

    int t = threadIdx.x;
    int wk = t >> 4;
    int wc = t & 15;
    int lrow = t >> 1;
    int lq = (t & 1) * 8;
    int row = bm0 + lrow;
    bool rv = row < M;
    const float* Ar = A + (size_t)row * K;

    float4 p0 = make_float4(0.f, 0.f, 0.f, 0.f), p1 = p0, wv = p0;

#define FETCHA(k0) do { \
    if (rv) { p0 = *(const float4*)(Ar + (k0) + lq); p1 = *(const float4*)(Ar + (k0) + lq + 4); } \
} while (0)
#define FETCHW(k0) do { wv = *(const float4*)(W + (size_t)((k0) + wk) * 64 + wc * 4); } while (0)
#define STAGEA(buf) do { \
    As[buf][lq + 0][lrow] = p0.x; As[buf][lq + 1][lrow] = p0.y; \
    As[buf][lq + 2][lrow] = p0.z; As[buf][lq + 3][lrow] = p0.w; \
    As[buf][lq + 4][lrow] = p1.x; As[buf][lq + 5][lrow] = p1.y; \
    As[buf][lq + 6][lrow] = p1.z; As[buf][lq + 7][lrow] = p1.w; \
} while (0)
#define STAGEW(buf) do { *(float4*)&Ws[buf][wk][wc * 4] = wv; } while (0)

    FETCHA(0); FETCHW(0);
    STAGEA(0); STAGEW(0);
    __syncthreads();

    float acc[8][4];
#pragma unroll
    for (int i = 0; i < 8; i++)
#pragma unroll
        for (int j = 0; j < 4; j++) acc[i][j] = 0.f;

    int tx = t & 15;
    int ty = t >> 4;
    int nt = K >> 4;

    for (int tile = 0; tile < nt; tile++) {
        int buf = tile & 1;
        if (tile + 1 < nt) { FETCHA((tile + 1) << 4); FETCHW((tile + 1) << 4); }

#pragma unroll
        for (int k = 0; k < 16; k++) {
            float4 b  = *(const float4*)&Ws[buf][k][tx * 4];
            float4 x0 = *(const float4*)&As[buf][k][ty * 8];
            float4 x1 = *(const float4*)&As[buf][k][ty * 8 + 4];
            acc[0][0] += x0.x * b.x; acc[0][1] += x0.x * b.y; acc[0][2] += x0.x * b.z; acc[0][3] += x0.x * b.w;
            acc[1][0] += x0.y * b.x; acc[1][1] += x0.y * b.y; acc[1][2] += x0.y * b.z; acc[1][3] += x0.y * b.w;
            acc[2][0] += x0.z * b.x; acc[2][1] += x0.z * b.y; acc[2][2] += x0.z * b.z; acc[2][3] += x0.z * b.w;
            acc[3][0] += x0.w * b.x; acc[3][1] += x0.w * b.y; acc[3][2] += x0.w * b.z; acc[3][3] += x0.w * b.w;
            acc[4][0] += x1.x * b.x; acc[4][1] += x1.x * b.y; acc[4][2] += x1.x * b.z; acc[4][3] += x1.x * b.w;
            acc[5][0] += x1.y * b.x; acc[5][1] += x1.y * b.y; acc[5][2] += x1.y * b.z; acc[5][3] += x1.y * b.w;
            acc[6][0] += x1.z * b.x; acc[6][1] += x1.z * b.y; acc[6][2] += x1.z * b.z; acc[6][3] += x1.z * b.w;
            acc[7][0] += x1.w * b.x; acc[7][1] += x1.w * b.y; acc[7][2] += x1.w * b.z; acc[7][3] += x1.w * b.w;
        }

        if (tile + 1 < nt) {
            __syncthreads();
            STAGEA((tile + 1) & 1);
            STAGEW((tile + 1) & 1);
            __syncthreads();
        }
    }

    float bvals[4] = {0.f, 0.f, 0.f, 0.f};
    if (bias) {
#pragma unroll
        for (int j = 0; j < 4; j++) bvals[j] = bias[tx * 4 + j];
    }

#pragma unroll
    for (int r = 0; r < 8; r++) {
        int orow = bm0 + ty * 8 + r;
        if (orow < M) {
            float4 v;
            v.x = acc[r][0] + bvals[0];
            v.y = acc[r][1] + bvals[1];
            v.z = acc[r][2] + bvals[2];
            v.w = acc[r][3] + bvals[3];
            if (doRelu) {
                v.x = fmaxf(v.x, 0.f); v.y = fmaxf(v.y, 0.f);
                v.z = fmaxf(v.z, 0.f); v.w = fmaxf(v.w, 0.f);
            }
            *(float4*)(C + (size_t)orow * 64 + tx * 4) = v;
            if (halfC) {
                halfC[(size_t)orow * 32 + tx * 2]     = __floats2half2_rn(v.x, v.y);
                halfC[(size_t)orow * 32 + tx * 2 + 1] = __floats2half2_rn(v.z, v.w);
            }
        }
    }
#undef FETCHA
#undef FETCHW
#undef STAGEA
#undef STAGEW
}

// ---------------- fused edge-stage + GEMM-chunk co-kernel ----------------
// stage 1 = degree count; stage 5 = CSR fill writing (src, onorm[src]) pairs
__global__ void __launch_bounds__(256, 4) csr_gemm_kernel(
    int stage, int nGemm, int gemmStart,
    const int* __restrict__ esrc, const int* __restrict__ edst,
    const float* __restrict__ A1, const float* __restrict__ W1, const float* __restrict__ b1,
    float* __restrict__ C1, __half2* __restrict__ H1, int M1,
    const float* __restrict__ A2, const float* __restrict__ W2, const float* __restrict__ b2,
    float* __restrict__ C2, __half2* __restrict__ H2, int M2,
    int K, int doRelu, int nb1, int nbTot)
{
    __shared__ char sh[24576];
    int tid = threadIdx.x;

    if ((int)blockIdx.x < nGemm) {
        int gb = gemmStart + blockIdx.x;
        if (gb < nbTot)
            gemm_body(gb, sh, A1, W1, b1, C1, H1, M1, A2, W2, b2, C2, H2, M2, K, doRelu, nb1);
        return;
    }
    int cb = blockIdx.x - nGemm;
    int base = (cb * 256 + tid) * 4;
    if (base >= NE) return;

    int4 s4 = *(const int4*)(esrc + base);
    int4 d4 = *(const int4*)(edst + base);
    if (stage == 1) {
        atomicAdd(&g_ocnt[s4.x], 1); atomicAdd(&g_icnt[d4.x], 1);
        atomicAdd(&g_ocnt[s4.y], 1); atomicAdd(&g_icnt[d4.y], 1);
        atomicAdd(&g_ocnt[s4.z], 1); atomicAdd(&g_icnt[d4.z], 1);
        atomicAdd(&g_ocnt[s4.w], 1); atomicAdd(&g_icnt[d4.w], 1);
    } else {
        float wx = g_onorm[s4.x], wy = g_onorm[s4.y];
        float wz = g_onorm[s4.z], ww = g_onorm[s4.w];
        g_cpair[atomicAdd(&g_cur[d4.x], 1)] = make_float2(__int_as_float(s4.x), wx);
        g_cpair[atomicAdd(&g_cur[d4.y], 1)] = make_float2(__int_as_float(s4.y), wy);
        g_cpair[atomicAdd(&g_cur[d4.z], 1)] = make_float2(__int_as_float(s4.z), wz);
        g_cpair[atomicAdd(&g_cur[d4.w], 1)] = make_float2(__int_as_float(s4.w), ww);
    }
}

// ---------------- standalone small kernels ----------------
__global__ void clear_kernel() {
    int i = blockIdx.x * blockDim.x + threadIdx.x;
    if (i < NN) { g_ocnt[i] = 0; g_icnt[i] = 0; }
}

__global__ void scan1_kernel() {
    __shared__ int wsum[8];
    int tid = threadIdx.x;
    int base = blockIdx.x * 1024 + tid * 4;
    int v0 = (base + 0 < NN) ? g_icnt[base + 0] : 0;
    int v1 = (base + 1 < NN) ? g_icnt[base + 1] : 0;
    int v2 = (base + 2 < NN) ? g_icnt[base + 2] : 0;
    int v3 = (base + 3 < NN) ? g_icnt[base + 3] : 0;
    int s1 = v0, s2 = v0 + v1, s3 = v0 + v1 + v2, s = s3 + v3;
    int lane = tid & 31, wp = tid >> 5;
    int incl = s;
#pragma unroll
    for (int o = 1; o < 32; o <<= 1) {
        int n = __shfl_up_sync(0xffffffffu, incl, o);
        if (lane >= o) incl += n;
    }
    if (lane == 31) wsum[wp] = incl;
    __syncthreads();
    int wbase = 0;
    for (int k = 0; k < wp; k++) wbase += wsum[k];
    int et = wbase + incl - s;
    if (base + 0 < NN) g_off[base + 0] = et;
    if (base + 1 < NN) g_off[base + 1] = et + s1;
    if (base + 2 < NN) g_off[base + 2] = et + s2;
    if (base + 3 < NN) g_off[base + 3] = et + s3;
    if (tid == 255) g_bsum[blockIdx.x] = wbase + incl;
}

__global__ void scan3_kernel() {
    __shared__ int sboff[SCAN_NBLK];
    __shared__ int wsum[4];
    int tid = threadIdx.x;
    if (tid < 128) {
        int v = (tid < SCAN_NBLK) ? g_bsum[tid] : 0;
        int lane = tid & 31, wp = tid >> 5;
        int incl = v;
#pragma unroll
        for (int o = 1; o < 32; o <<= 1) {
            int n = __shfl_up_sync(0xffffffffu, incl, o);
            if (lane >= o) incl += n;
        }
        if (lane == 31) wsum[wp] = incl;
        __syncthreads();
        int wbase = 0;
        for (int k = 0; k < wp; k++) wbase += wsum[k];
        if (tid < SCAN_NBLK) sboff[tid] = wbase + incl - v;
    } else {
        __syncthreads();
    }
    __syncthreads();
    int i = blockIdx.x * blockDim.x + tid;
    if (i < NN) {
        int o = g_off[i] + sboff[i >> 10];
        g_off[i] = o;
        g_cur[i] = o;
        float od = fmaxf((float)g_ocnt[i], 1.0f);
        g_onorm[i]  = rsqrtf(od);
        g_rodeg[i]  = sqrtf(od);
        g_innorm[i] = rsqrtf(fmaxf((float)g_icnt[i], 1.0f));
    }
}

// ---------------- plain dual GEMM ----------------
__global__ void __launch_bounds__(256, 4) gemm_dual(
    const float* __restrict__ A1, const float* __restrict__ W1, const float* __restrict__ b1,
    float* __restrict__ C1, int M1,
    const float* __restrict__ A2, const float* __restrict__ W2, const float* __restrict__ b2,
    float* __restrict__ C2, int M2,
    int K, int doRelu, int nb1)
{
    __shared__ char sh[24576];
    gemm_body(blockIdx.x, sh, A1, W1, b1, C1, nullptr, M1, A2, W2, b2, C2, nullptr, M2, K, doRelu, nb1);
}

// ---------------- GCN layer 1: warp/node, fp16 neighbor rows, paired CSR ----------------
// agg0s = onorm * inn * sum(e0[src]*onorm[src]); writes fp32 + fp16 mirror
__global__ void gather1_kernel() {
    int gw = (blockIdx.x * blockDim.x + threadIdx.x) >> 5;
    int lane = threadIdx.x & 31;
    if (gw >= NN) return;
    int start = g_off[gw];
    int deg = g_icnt[gw];
    float a0 = 0.f, a1 = 0.f;
    int nfull = deg & ~31;
    for (int j0 = 0; j0 < nfull; j0 += 32) {
        float2 pr = g_cpair[start + j0 + lane];
        int idx = __float_as_int(pr.x);
        float w = pr.y;
#pragma unroll
        for (int jj = 0; jj < 32; jj++) {
            int   s  = __shfl_sync(0xffffffffu, idx, jj);
            float wv = __shfl_sync(0xffffffffu, w, jj);
            float2 r = __half22float2(g_e0h[(size_t)s * 32 + lane]);
            a0 += wv * r.x;
            a1 += wv * r.y;
        }
    }
    int rem = deg - nfull;
    if (rem) {
        int idx = 0; float w = 0.f;
        if (lane < rem) {
            float2 pr = g_cpair[start + nfull + lane];
            idx = __float_as_int(pr.x);
            w = pr.y;
        }
        for (int jj = 0; jj < rem; jj++) {
            int   s  = __shfl_sync(0xffffffffu, idx, jj);
            float wv = __shfl_sync(0xffffffffu, w, jj);
            float2 r = __half22float2(g_e0h[(size_t)s * 32 + lane]);
            a0 += wv * r.x;
            a1 += wv * r.y;
        }
    }
    float sc = g_innorm[gw] * g_onorm[gw];
    float2 v = make_float2(a0 * sc, a1 * sc);
    *(float2*)(g_agg0s + (size_t)gw * 64 + 2 * lane) = v;
    g_agg0sh[(size_t)gw * 32 + lane] = __floats2half2_rn(v.x, v.y);
}

// ---------------- GCN layer 2 + final combine (fp16 neighbor rows) ----------------
// out[n] = e0 + 0.5*(agg0s*rodeg) + (1/3)*inn*sum(agg0s[src]) (+side for items)
__global__ void gather2_final_kernel(const float* __restrict__ side, float* __restrict__ out) {
    int gw = (blockIdx.x * blockDim.x + threadIdx.x) >> 5;
    int lane = threadIdx.x & 31;
    if (gw >= NN) return;
    int start = g_off[gw];
    int deg = g_icnt[gw];
    float a0 = 0.f, a1 = 0.f;
    int nfull = deg & ~31;
    for (int j0 = 0; j0 < nfull; j0 += 32) {
        int idx = __float_as_int(g_cpair[start + j0 + lane].x);
#pragma unroll
        for (int jj = 0; jj < 32; jj++) {
            int s = __shfl_sync(0xffffffffu, idx, jj);
            float2 r = __half22float2(g_agg0sh[(size_t)s * 32 + lane]);
            a0 += r.x;
            a1 += r.y;
        }
    }
    int rem = deg - nfull;
    if (rem) {
        int idx = 0;
        if (lane < rem) idx = __float_as_int(g_cpair[start + nfull + lane].x);
        for (int jj = 0; jj < rem; jj++) {
            int s = __shfl_sync(0xffffffffu, idx, jj);
            float2 r = __half22float2(g_agg0sh[(size_t)s * 32 + lane]);
            a0 += r.x;
            a1 += r.y;
        }
    }
    float inn3 = g_innorm[gw] * (1.0f / 3.0f);
    float half_rodeg = 0.5f * g_rodeg[gw];
    size_t base = (size_t)gw * 64 + 2 * lane;
    float2 e = *(const float2*)(g_e0 + base);
    float2 m = *(const float2*)(g_agg0s + base);
    float r0v = e.x + half_rodeg * m.x + inn3 * a0;
    float r1v = e.y + half_rodeg * m.y + inn3 * a1;
    if (gw >= NU) {
        float2 sd = *(const float2*)(side + (size_t)(gw - NU) * 64 + 2 * lane);
        r0v += sd.x;
        r1v += sd.y;
    }
    *(float2*)(out + base) = make_float2(r0v, r1v);
}

// ---------------- decode epilogue (float2 gathers) ----------------
__global__ void decode_kernel(const float* __restrict__ Tf, const float* __restrict__ Tcf,
                              const float* __restrict__ W1, const float* __restrict__ W2,
                              const int* __restrict__ userId, const int* __restrict__ posId,
                              const int* __restrict__ negId,
                              float* __restrict__ of, float* __restrict__ ocf) {
    __shared__ float w2s[64];
    __shared__ float w1l[64];
    int t = threadIdx.x;
    if (t < 64) {
        w2s[t] = W2[t];
        w1l[t] = W1[128 * 64 + t];
    }
    __syncthreads();

    int warp = t >> 5, lane = t & 31;
    int pair = blockIdx.x * 8 + warp;
    if (pair >= NP) return;

    int u  = userId[pair];
    int p  = posId[pair];
    int ng = negId[pair];

    float2 uv = *(const float2*)(g_xu + (size_t)u * 64 + 2 * lane);
    float2 pv = *(const float2*)(g_xi + (size_t)p * 64 + 2 * lane);
    float2 nv = *(const float2*)(g_xi + (size_t)ng * 64 + 2 * lane);
    float2 wl = *(const float2*)(w1l + 2 * lane);
    float2 w2 = *(const float2*)(w2s + 2 * lane);

    float tfp = Tf[pair],  tfn = Tf[pair + NP];
    float tcp = Tcf[pair], tcn = Tcf[pair + NP];

    auto combo = [&](float j0, float j1, float T) -> float {
        float x0 = uv.x + j0 + T * wl.x;
        float x1 = uv.y + j1 + T * wl.y;
        float e0 = x0 > 0.f ? x0 : (expf(x0) - 1.0f);
        float e1 = x1 > 0.f ? x1 : (expf(x1) - 1.0f);
        float s = e0 * w2.x + e1 * w2.y;
        s += __shfl_down_sync(0xffffffffu, s, 16);
        s += __shfl_down_sync(0xffffffffu, s, 8);
        s += __shfl_down_sync(0xffffffffu, s, 4);
        s += __shfl_down_sync(0xffffffffu, s, 2);
        s += __shfl_down_sync(0xffffffffu, s, 1);
        return s;
    };

    float rf_p = combo(pv.x, pv.y, tfp);
    float rf_n = combo(nv.x, nv.y, tfn);
    float rc_p = combo(pv.x, pv.y, tcp);
    float rc_n = combo(nv.x, nv.y, tcn);

    if (lane == 0) {
        of[pair]       = rf_p;
        of[pair + NP]  = rf_n;
        ocf[pair]      = rc_p;
        ocf[pair + NP] = rc_n;
    }
}

// ---------------- launch ----------------
extern "C" void kernel_launch(void* const* d_in, const int* in_sizes, int n_in,
                              void* d_out, int out_size) {
    const float* userF = (const float*)d_in[0];
    const float* itemF = (const float*)d_in[1];
    const float* side  = (const float*)d_in[2];
    const float* Tf    = (const float*)d_in[3];
    const float* Tcf   = (const float*)d_in[4];
    const float* Wu    = (const float*)d_in[5];
    const float* bu    = (const float*)d_in[6];
    const float* Wi    = (const float*)d_in[7];
    const float* bi    = (const float*)d_in[8];
    const float* W1    = (const float*)d_in[9];
    const float* b1    = (const float*)d_in[10];
    const float* W2    = (const float*)d_in[11];
    const int* esrc    = (const int*)d_in[12];
    const int* edst    = (const int*)d_in[13];
    const int* userId  = (const int*)d_in[14];
    const int* posId   = (const int*)d_in[15];
    const int* negId   = (const int*)d_in[16];

    float* out   = (float*)d_out;
    float* outI  = out + (size_t)NU * H;
    float* outLF = out + (size_t)NN * H;
    float* outLC = outLF + 2 * NP;

    float *pe0, *pxu, *pxi;
    __half2 *pe0h;
    cudaGetSymbolAddress((void**)&pe0, g_e0);
    cudaGetSymbolAddress((void**)&pe0h, g_e0h);
    cudaGetSymbolAddress((void**)&pxu, g_xu);
    cudaGetSymbolAddress((void**)&pxi, g_xi);

    int nb1 = (NU + 127) / 128;            // 391
    int nb2 = (NI + 127) / 128;            // 391
    int nbTot = nb1 + nb2;                 // 782
    int edgeBlocks = (NE / 4 + 255) / 256; // 1563

    clear_kernel<<<(NN + 255) / 256, 256>>>();

    // degree stage fused with first 300 GEMM blocks
    csr_gemm_kernel<<<300 + edgeBlocks, 256>>>(
        1, 300, 0, esrc, edst,
        userF, Wu, bu, pe0, pe0h, NU,
        itemF, Wi, bi, pe0 + (size_t)NU * H, pe0h + (size_t)NU * 32, NI,
        128, 1, nb1, nbTot);

    scan1_kernel<<<SCAN_NBLK, 256>>>();
    scan3_kernel<<<(NN + 255) / 256, 256>>>();

    // fill stage (writes (src, w) pairs) fused with remaining 482 GEMM blocks
    csr_gemm_kernel<<<482 + edgeBlocks, 256>>>(
        5, 482, 300, esrc, edst,
        userF, Wu, bu, pe0, pe0h, NU,
        itemF, Wi, bi, pe0 + (size_t)NU * H, pe0h + (size_t)NU * 32, NI,
        128, 1, nb1, nbTot);

    // GCN layers
    gather1_kernel<<<(NN * 32 + 255) / 256, 256>>>();
    gather2_final_kernel<<<(NN * 32 + 255) / 256, 256>>>(side, out);

    // per-node decode transforms
    gemm_dual<<<nbTot, 256>>>(out,  W1,           b1,      pxu, NU,
                              outI, W1 + 64 * 64, nullptr, pxi, NI,
                              64, 0, nb1);

    // decode epilogue
    decode_kernel<<<(NP + 7) / 8, 256>>>(Tf, Tcf, W1, W2, userId, posId, negId, outLF, outLC);
}

// round 11
// speedup vs baseline: 1.6254x; 1.1567x over previous
#include <cuda_runtime.h>
#include <cuda_fp16.h>
#include <math.h>

#define NU 50000
#define NI 50000
#define NN 100000
#define NE 1600000
#define NP 200000
#define H  64
#define SCAN_NBLK ((NN + 1023) / 1024)   // 98

// ---------------- device scratch ----------------
__device__ int   g_ocnt[NN];
__device__ int   g_icnt[NN];
__device__ float g_onorm[NN];
__device__ float g_innorm[NN];
__device__ float g_rodeg[NN];               // sqrt(max(out_deg,1))
__device__ int   g_off[NN];
__device__ int   g_cur[NN];
__device__ int   g_bsum[SCAN_NBLK];
__device__ float2 g_cpair[NE];              // (src as int bits, onorm[src])
__device__ float g_e0[(size_t)NN * H];
__device__ __half2 g_e0h[(size_t)NN * 32];      // fp16 mirror of e0 (gather reads)
__device__ float g_agg0s[(size_t)NN * H];   // layer-1 out, prescaled by onorm (fp32)
__device__ __half2 g_agg0sh[(size_t)NN * 32];   // fp16 mirror (gather reads)
__device__ float g_xu[(size_t)NU * H];
__device__ float g_xi[(size_t)NI * H];

// ---------------- tf32 helpers ----------------
__device__ __forceinline__ float to_tf32(float x) {
    float r;
    asm("cvt.rna.tf32.f32 %0, %1;" : "=f"(r) : "f"(x));
    return r;
}

__device__ __forceinline__ void mma_tf32(float c[4],
                                         unsigned a0, unsigned a1, unsigned a2, unsigned a3,
                                         unsigned b0, unsigned b1) {
    asm volatile(
        "mma.sync.aligned.m16n8k8.row.col.f32.tf32.tf32.f32 "
        "{%0,%1,%2,%3},{%4,%5,%6,%7},{%8,%9},{%0,%1,%2,%3};"
        : "+f"(c[0]), "+f"(c[1]), "+f"(c[2]), "+f"(c[3])
        : "r"(a0), "r"(a1), "r"(a2), "r"(a3), "r"(b0), "r"(b1));
}

// ---------------- tensor-core GEMM body (tf32 mma, fp32 accum) ----------------
// C[M x 64] = A[M x K] @ W[K x 64]; 128x64 block tile, 8 warps (m16 each).
// sh layout: Ws[2][16][88] at 0 (11264B), As[2][16][136] at 11264 (17408B). Total 28672B.
#define WS_STRIDE 88
#define AS_STRIDE 136
__device__ __forceinline__ void gemm_body(
    int gb, char* sh,
    const float* __restrict__ A1, const float* __restrict__ W1, const float* __restrict__ b1,
    float* __restrict__ C1, __half2* __restrict__ H1, int M1,
    const float* __restrict__ A2, const float* __restrict__ W2, const float* __restrict__ b2,
    float* __restrict__ C2, __half2* __restrict__ H2, int M2,
    int K, int doRelu, int nb1)
{
    float (*Ws)[16][WS_STRIDE] = (float(*)[16][WS_STRIDE])sh;
    float (*As)[16][AS_STRIDE] = (float(*)[16][AS_STRIDE])(sh + 11264);

    const float* A; const float* W; const float* bias; float* C; __half2* halfC; int M, bm0;
    if (gb < nb1) {
        A = A1; W = W1; bias = b1; C = C1; halfC = H1; M = M1; bm0 = gb * 128;
    } else {
        A = A2; W = W2; bias = b2; C = C2; halfC = H2; M = M2; bm0 = (gb - nb1) * 128;
    }

    int t = threadIdx.x;
    int wk = t >> 4;          // W-tile k row (0..15)
    int wc = t & 15;          // W-tile col quad
    int lrow = t >> 1;        // A-tile row (0..127)
    int lq = (t & 1) * 8;     // A-tile k offset
    int row = bm0 + lrow;
    bool rv = row < M;
    const float* Ar = A + (size_t)row * K;

    float4 p0 = make_float4(0.f, 0.f, 0.f, 0.f), p1 = p0, wv = p0;

#define FETCHA(k0) do { \
    if (rv) { p0 = *(const float4*)(Ar + (k0) + lq); p1 = *(const float4*)(Ar + (k0) + lq + 4); } \
} while (0)
#define FETCHW(k0) do { wv = *(const float4*)(W + (size_t)((k0) + wk) * 64 + wc * 4); } while (0)
#define STAGEA(buf) do { \
    As[buf][lq + 0][lrow] = to_tf32(p0.x); As[buf][lq + 1][lrow] = to_tf32(p0.y); \
    As[buf][lq + 2][lrow] = to_tf32(p0.z); As[buf][lq + 3][lrow] = to_tf32(p0.w); \
    As[buf][lq + 4][lrow] = to_tf32(p1.x); As[buf][lq + 5][lrow] = to_tf32(p1.y); \
    As[buf][lq + 6][lrow] = to_tf32(p1.z); As[buf][lq + 7][lrow] = to_tf32(p1.w); \
} while (0)
#define STAGEW(buf) do { \
    Ws[buf][wk][wc * 4 + 0] = to_tf32(wv.x); Ws[buf][wk][wc * 4 + 1] = to_tf32(wv.y); \
    Ws[buf][wk][wc * 4 + 2] = to_tf32(wv.z); Ws[buf][wk][wc * 4 + 3] = to_tf32(wv.w); \
} while (0)

    FETCHA(0); FETCHW(0);
    STAGEA(0); STAGEW(0);
    __syncthreads();

    float acc[8][4];
#pragma unroll
    for (int i = 0; i < 8; i++)
#pragma unroll
        for (int j = 0; j < 4; j++) acc[i][j] = 0.f;

    int warp = t >> 5, lane = t & 31;
    int gid = lane >> 2;      // 0..7
    int tig = lane & 3;       // 0..3
    int warpRow = warp * 16;
    int nt = K >> 4;

    for (int tile = 0; tile < nt; tile++) {
        int buf = tile & 1;
        if (tile + 1 < nt) { FETCHA((tile + 1) << 4); FETCHW((tile + 1) << 4); }

#pragma unroll
        for (int ks = 0; ks < 16; ks += 8) {
            unsigned a0 = __float_as_uint(As[buf][ks + tig    ][warpRow + gid]);
            unsigned a1 = __float_as_uint(As[buf][ks + tig    ][warpRow + gid + 8]);
            unsigned a2 = __float_as_uint(As[buf][ks + tig + 4][warpRow + gid]);
            unsigned a3 = __float_as_uint(As[buf][ks + tig + 4][warpRow + gid + 8]);
#pragma unroll
            for (int n = 0; n < 8; n++) {
                unsigned b0 = __float_as_uint(Ws[buf][ks + tig    ][n * 8 + gid]);
                unsigned b1 = __float_as_uint(Ws[buf][ks + tig + 4][n * 8 + gid]);
                mma_tf32(acc[n], a0, a1, a2, a3, b0, b1);
            }
        }

        if (tile + 1 < nt) {
            __syncthreads();
            STAGEA((tile + 1) & 1);
            STAGEW((tile + 1) & 1);
            __syncthreads();
        }
    }

    // epilogue: c0/c1 -> row warpRow+gid, cols 2*tig,2*tig+1 of each n-tile; c2/c3 -> row+8
    int r0 = bm0 + warpRow + gid;
    int r1 = r0 + 8;
#pragma unroll
    for (int n = 0; n < 8; n++) {
        int col = n * 8 + 2 * tig;
        float bx = 0.f, by = 0.f;
        if (bias) { float2 bb = *(const float2*)(bias + col); bx = bb.x; by = bb.y; }
        float v0 = acc[n][0] + bx, v1 = acc[n][1] + by;
        float v2 = acc[n][2] + bx, v3 = acc[n][3] + by;
        if (doRelu) {
            v0 = fmaxf(v0, 0.f); v1 = fmaxf(v1, 0.f);
            v2 = fmaxf(v2, 0.f); v3 = fmaxf(v3, 0.f);
        }
        if (r0 < M) {
            *(float2*)(C + (size_t)r0 * 64 + col) = make_float2(v0, v1);
            if (halfC) halfC[(size_t)r0 * 32 + col / 2] = __floats2half2_rn(v0, v1);
        }
        if (r1 < M) {
            *(float2*)(C + (size_t)r1 * 64 + col) = make_float2(v2, v3);
            if (halfC) halfC[(size_t)r1 * 32 + col / 2] = __floats2half2_rn(v2, v3);
        }
    }
#undef FETCHA
#undef FETCHW
#undef STAGEA
#undef STAGEW
}

// ---------------- fused edge-stage + GEMM-chunk co-kernel ----------------
// stage 1 = degree count; stage 5 = CSR fill writing (src, onorm[src]) pairs
__global__ void __launch_bounds__(256, 3) csr_gemm_kernel(
    int stage, int nGemm, int gemmStart,
    const int* __restrict__ esrc, const int* __restrict__ edst,
    const float* __restrict__ A1, const float* __restrict__ W1, const float* __restrict__ b1,
    float* __restrict__ C1, __half2* __restrict__ H1, int M1,
    const float* __restrict__ A2, const float* __restrict__ W2, const float* __restrict__ b2,
    float* __restrict__ C2, __half2* __restrict__ H2, int M2,
    int K, int doRelu, int nb1, int nbTot)
{
    __shared__ char sh[28672];
    int tid = threadIdx.x;

    if ((int)blockIdx.x < nGemm) {
        int gb = gemmStart + blockIdx.x;
        if (gb < nbTot)
            gemm_body(gb, sh, A1, W1, b1, C1, H1, M1, A2, W2, b2, C2, H2, M2, K, doRelu, nb1);
        return;
    }
    int cb = blockIdx.x - nGemm;
    int base = (cb * 256 + tid) * 4;
    if (base >= NE) return;

    int4 s4 = *(const int4*)(esrc + base);
    int4 d4 = *(const int4*)(edst + base);
    if (stage == 1) {
        atomicAdd(&g_ocnt[s4.x], 1); atomicAdd(&g_icnt[d4.x], 1);
        atomicAdd(&g_ocnt[s4.y], 1); atomicAdd(&g_icnt[d4.y], 1);
        atomicAdd(&g_ocnt[s4.z], 1); atomicAdd(&g_icnt[d4.z], 1);
        atomicAdd(&g_ocnt[s4.w], 1); atomicAdd(&g_icnt[d4.w], 1);
    } else {
        float wx = g_onorm[s4.x], wy = g_onorm[s4.y];
        float wz = g_onorm[s4.z], ww = g_onorm[s4.w];
        g_cpair[atomicAdd(&g_cur[d4.x], 1)] = make_float2(__int_as_float(s4.x), wx);
        g_cpair[atomicAdd(&g_cur[d4.y], 1)] = make_float2(__int_as_float(s4.y), wy);
        g_cpair[atomicAdd(&g_cur[d4.z], 1)] = make_float2(__int_as_float(s4.z), wz);
        g_cpair[atomicAdd(&g_cur[d4.w], 1)] = make_float2(__int_as_float(s4.w), ww);
    }
}

// ---------------- standalone small kernels ----------------
__global__ void clear_kernel() {
    int i = blockIdx.x * blockDim.x + threadIdx.x;
    if (i < NN) { g_ocnt[i] = 0; g_icnt[i] = 0; }
}

__global__ void scan1_kernel() {
    __shared__ int wsum[8];
    int tid = threadIdx.x;
    int base = blockIdx.x * 1024 + tid * 4;
    int v0 = (base + 0 < NN) ? g_icnt[base + 0] : 0;
    int v1 = (base + 1 < NN) ? g_icnt[base + 1] : 0;
    int v2 = (base + 2 < NN) ? g_icnt[base + 2] : 0;
    int v3 = (base + 3 < NN) ? g_icnt[base + 3] : 0;
    int s1 = v0, s2 = v0 + v1, s3 = v0 + v1 + v2, s = s3 + v3;
    int lane = tid & 31, wp = tid >> 5;
    int incl = s;
#pragma unroll
    for (int o = 1; o < 32; o <<= 1) {
        int n = __shfl_up_sync(0xffffffffu, incl, o);
        if (lane >= o) incl += n;
    }
    if (lane == 31) wsum[wp] = incl;
    __syncthreads();
    int wbase = 0;
    for (int k = 0; k < wp; k++) wbase += wsum[k];
    int et = wbase + incl - s;
    if (base + 0 < NN) g_off[base + 0] = et;
    if (base + 1 < NN) g_off[base + 1] = et + s1;
    if (base + 2 < NN) g_off[base + 2] = et + s2;
    if (base + 3 < NN) g_off[base + 3] = et + s3;
    if (tid == 255) g_bsum[blockIdx.x] = wbase + incl;
}

__global__ void scan3_kernel() {
    __shared__ int sboff[SCAN_NBLK];
    __shared__ int wsum[4];
    int tid = threadIdx.x;
    if (tid < 128) {
        int v = (tid < SCAN_NBLK) ? g_bsum[tid] : 0;
        int lane = tid & 31, wp = tid >> 5;
        int incl = v;
#pragma unroll
        for (int o = 1; o < 32; o <<= 1) {
            int n = __shfl_up_sync(0xffffffffu, incl, o);
            if (lane >= o) incl += n;
        }
        if (lane == 31) wsum[wp] = incl;
        __syncthreads();
        int wbase = 0;
        for (int k = 0; k < wp; k++) wbase += wsum[k];
        if (tid < SCAN_NBLK) sboff[tid] = wbase + incl - v;
    } else {
        __syncthreads();
    }
    __syncthreads();
    int i = blockIdx.x * blockDim.x + tid;
    if (i < NN) {
        int o = g_off[i] + sboff[i >> 10];
        g_off[i] = o;
        g_cur[i] = o;
        float od = fmaxf((float)g_ocnt[i], 1.0f);
        g_onorm[i]  = rsqrtf(od);
        g_rodeg[i]  = sqrtf(od);
        g_innorm[i] = rsqrtf(fmaxf((float)g_icnt[i], 1.0f));
    }
}

// ---------------- plain dual GEMM ----------------
__global__ void __launch_bounds__(256, 3) gemm_dual(
    const float* __restrict__ A1, const float* __restrict__ W1, const float* __restrict__ b1,
    float* __restrict__ C1, int M1,
    const float* __restrict__ A2, const float* __restrict__ W2, const float* __restrict__ b2,
    float* __restrict__ C2, int M2,
    int K, int doRelu, int nb1)
{
    __shared__ char sh[28672];
    gemm_body(blockIdx.x, sh, A1, W1, b1, C1, nullptr, M1, A2, W2, b2, C2, nullptr, M2, K, doRelu, nb1);
}

// ---------------- GCN layer 1: warp/node, fp16 neighbor rows, paired CSR ----------------
__global__ void gather1_kernel() {
    int gw = (blockIdx.x * blockDim.x + threadIdx.x) >> 5;
    int lane = threadIdx.x & 31;
    if (gw >= NN) return;
    int start = g_off[gw];
    int deg = g_icnt[gw];
    float a0 = 0.f, a1 = 0.f;
    int nfull = deg & ~31;
    for (int j0 = 0; j0 < nfull; j0 += 32) {
        float2 pr = g_cpair[start + j0 + lane];
        int idx = __float_as_int(pr.x);
        float w = pr.y;
#pragma unroll
        for (int jj = 0; jj < 32; jj++) {
            int   s  = __shfl_sync(0xffffffffu, idx, jj);
            float wv = __shfl_sync(0xffffffffu, w, jj);
            float2 r = __half22float2(g_e0h[(size_t)s * 32 + lane]);
            a0 += wv * r.x;
            a1 += wv * r.y;
        }
    }
    int rem = deg - nfull;
    if (rem) {
        int idx = 0; float w = 0.f;
        if (lane < rem) {
            float2 pr = g_cpair[start + nfull + lane];
            idx = __float_as_int(pr.x);
            w = pr.y;
        }
        for (int jj = 0; jj < rem; jj++) {
            int   s  = __shfl_sync(0xffffffffu, idx, jj);
            float wv = __shfl_sync(0xffffffffu, w, jj);
            float2 r = __half22float2(g_e0h[(size_t)s * 32 + lane]);
            a0 += wv * r.x;
            a1 += wv * r.y;
        }
    }
    float sc = g_innorm[gw] * g_onorm[gw];
    float2 v = make_float2(a0 * sc, a1 * sc);
    *(float2*)(g_agg0s + (size_t)gw * 64 + 2 * lane) = v;
    g_agg0sh[(size_t)gw * 32 + lane] = __floats2half2_rn(v.x, v.y);
}

// ---------------- GCN layer 2 + final combine (fp16 neighbor rows) ----------------
__global__ void gather2_final_kernel(const float* __restrict__ side, float* __restrict__ out) {
    int gw = (blockIdx.x * blockDim.x + threadIdx.x) >> 5;
    int lane = threadIdx.x & 31;
    if (gw >= NN) return;
    int start = g_off[gw];
    int deg = g_icnt[gw];
    float a0 = 0.f, a1 = 0.f;
    int nfull = deg & ~31;
    for (int j0 = 0; j0 < nfull; j0 += 32) {
        int idx = __float_as_int(g_cpair[start + j0 + lane].x);
#pragma unroll
        for (int jj = 0; jj < 32; jj++) {
            int s = __shfl_sync(0xffffffffu, idx, jj);
            float2 r = __half22float2(g_agg0sh[(size_t)s * 32 + lane]);
            a0 += r.x;
            a1 += r.y;
        }
    }
    int rem = deg - nfull;
    if (rem) {
        int idx = 0;
        if (lane < rem) idx = __float_as_int(g_cpair[start + nfull + lane].x);
        for (int jj = 0; jj < rem; jj++) {
            int s = __shfl_sync(0xffffffffu, idx, jj);
            float2 r = __half22float2(g_agg0sh[(size_t)s * 32 + lane]);
            a0 += r.x;
            a1 += r.y;
        }
    }
    float inn3 = g_innorm[gw] * (1.0f / 3.0f);
    float half_rodeg = 0.5f * g_rodeg[gw];
    size_t base = (size_t)gw * 64 + 2 * lane;
    float2 e = *(const float2*)(g_e0 + base);
    float2 m = *(const float2*)(g_agg0s + base);
    float r0v = e.x + half_rodeg * m.x + inn3 * a0;
    float r1v = e.y + half_rodeg * m.y + inn3 * a1;
    if (gw >= NU) {
        float2 sd = *(const float2*)(side + (size_t)(gw - NU) * 64 + 2 * lane);
        r0v += sd.x;
        r1v += sd.y;
    }
    *(float2*)(out + base) = make_float2(r0v, r1v);
}

// ---------------- decode epilogue (float2 gathers) ----------------
__global__ void decode_kernel(const float* __restrict__ Tf, const float* __restrict__ Tcf,
                              const float* __restrict__ W1, const float* __restrict__ W2,
                              const int* __restrict__ userId, const int* __restrict__ posId,
                              const int* __restrict__ negId,
                              float* __restrict__ of, float* __restrict__ ocf) {
    __shared__ float w2s[64];
    __shared__ float w1l[64];
    int t = threadIdx.x;
    if (t < 64) {
        w2s[t] = W2[t];
        w1l[t] = W1[128 * 64 + t];
    }
    __syncthreads();

    int warp = t >> 5, lane = t & 31;
    int pair = blockIdx.x * 8 + warp;
    if (pair >= NP) return;

    int u  = userId[pair];
    int p  = posId[pair];
    int ng = negId[pair];

    float2 uv = *(const float2*)(g_xu + (size_t)u * 64 + 2 * lane);
    float2 pv = *(const float2*)(g_xi + (size_t)p * 64 + 2 * lane);
    float2 nv = *(const float2*)(g_xi + (size_t)ng * 64 + 2 * lane);
    float2 wl = *(const float2*)(w1l + 2 * lane);
    float2 w2 = *(const float2*)(w2s + 2 * lane);

    float tfp = Tf[pair],  tfn = Tf[pair + NP];
    float tcp = Tcf[pair], tcn = Tcf[pair + NP];

    auto combo = [&](float j0, float j1, float T) -> float {
        float x0 = uv.x + j0 + T * wl.x;
        float x1 = uv.y + j1 + T * wl.y;
        float e0 = x0 > 0.f ? x0 : (expf(x0) - 1.0f);
        float e1 = x1 > 0.f ? x1 : (expf(x1) - 1.0f);
        float s = e0 * w2.x + e1 * w2.y;
        s += __shfl_down_sync(0xffffffffu, s, 16);
        s += __shfl_down_sync(0xffffffffu, s, 8);
        s += __shfl_down_sync(0xffffffffu, s, 4);
        s += __shfl_down_sync(0xffffffffu, s, 2);
        s += __shfl_down_sync(0xffffffffu, s, 1);
        return s;
    };

    float rf_p = combo(pv.x, pv.y, tfp);
    float rf_n = combo(nv.x, nv.y, tfn);
    float rc_p = combo(pv.x, pv.y, tcp);
    float rc_n = combo(nv.x, nv.y, tcn);

    if (lane == 0) {
        of[pair]       = rf_p;
        of[pair + NP]  = rf_n;
        ocf[pair]      = rc_p;
        ocf[pair + NP] = rc_n;
    }
}

// ---------------- launch ----------------
extern "C" void kernel_launch(void* const* d_in, const int* in_sizes, int n_in,
                              void* d_out, int out_size) {
    const float* userF = (const float*)d_in[0];
    const float* itemF = (const float*)d_in[1];
    const float* side  = (const float*)d_in[2];
    const float* Tf    = (const float*)d_in[3];
    const float* Tcf   = (const float*)d_in[4];
    const float* Wu    = (const float*)d_in[5];
    const float* bu    = (const float*)d_in[6];
    const float* Wi    = (const float*)d_in[7];
    const float* bi    = (const float*)d_in[8];
    const float* W1    = (const float*)d_in[9];
    const float* b1    = (const float*)d_in[10];
    const float* W2    = (const float*)d_in[11];
    const int* esrc    = (const int*)d_in[12];
    const int* edst    = (const int*)d_in[13];
    const int* userId  = (const int*)d_in[14];
    const int* posId   = (const int*)d_in[15];
    const int* negId   = (const int*)d_in[16];

    float* out   = (float*)d_out;
    float* outI  = out + (size_t)NU * H;
    float* outLF = out + (size_t)NN * H;
    float* outLC = outLF + 2 * NP;

    float *pe0, *pxu, *pxi;
    __half2 *pe0h;
    cudaGetSymbolAddress((void**)&pe0, g_e0);
    cudaGetSymbolAddress((void**)&pe0h, g_e0h);
    cudaGetSymbolAddress((void**)&pxu, g_xu);
    cudaGetSymbolAddress((void**)&pxi, g_xi);

    int nb1 = (NU + 127) / 128;            // 391
    int nb2 = (NI + 127) / 128;            // 391
    int nbTot = nb1 + nb2;                 // 782
    int edgeBlocks = (NE / 4 + 255) / 256; // 1563

    clear_kernel<<<(NN + 255) / 256, 256>>>();

    // degree stage fused with first 300 GEMM blocks
    csr_gemm_kernel<<<300 + edgeBlocks, 256>>>(
        1, 300, 0, esrc, edst,
        userF, Wu, bu, pe0, pe0h, NU,
        itemF, Wi, bi, pe0 + (size_t)NU * H, pe0h + (size_t)NU * 32, NI,
        128, 1, nb1, nbTot);

    scan1_kernel<<<SCAN_NBLK, 256>>>();
    scan3_kernel<<<(NN + 255) / 256, 256>>>();

    // fill stage (writes (src, w) pairs) fused with remaining 482 GEMM blocks
    csr_gemm_kernel<<<482 + edgeBlocks, 256>>>(
        5, 482, 300, esrc, edst,
        userF, Wu, bu, pe0, pe0h, NU,
        itemF, Wi, bi, pe0 + (size_t)NU * H, pe0h + (size_t)NU * 32, NI,
        128, 1, nb1, nbTot);

    // GCN layers
    gather1_kernel<<<(NN * 32 + 255) / 256, 256>>>();
    gather2_final_kernel<<<(NN * 32 + 255) / 256, 256>>>(side, out);

    // per-node decode transforms
    gemm_dual<<<nbTot, 256>>>(out,  W1,           b1,      pxu, NU,
                              outI, W1 + 64 * 64, nullptr, pxi, NI,
                              64, 0, nb1);

    // decode epilogue
    decode_kernel<<<(NP + 7) / 8, 256>>>(Tf, Tcf, W1, W2, userId, posId, negId, outLF, outLC);
}